// round 8
// baseline (speedup 1.0000x reference)
#include <cuda_runtime.h>
#include <cuda_bf16.h>
#include <cstdint>

// ---------------- problem constants ----------------
#define NT 131072     // tokens
#define DM 2048       // d_model
#define DH 256        // d_hid
#define NH 16         // heads
#define WMAX 64       // window

// ---------------- scratch (device globals; no allocs allowed) ----------------
__device__ __nv_bfloat16 g_w1bT[(size_t)DH * DM];  // [n][k] bf16
__device__ float g_qvs[DH * 32];                   // [c][j] j<16 -> q[j][c], j>=16 -> v[j-16][c]
__device__ float g_logitsT[(size_t)NH * NT];       // [h][token]
__device__ float g_valsT[(size_t)NH * NT];         // [h][token]
__device__ unsigned int g_headmax[NH];             // order-preserving float keys

// ---------------- helpers ----------------
__device__ __forceinline__ uint32_t smem_u32(const void* p) {
    uint32_t a;
    asm("{ .reg .u64 t; cvta.to.shared.u64 t, %1; cvt.u32.u64 %0, t; }" : "=r"(a) : "l"(p));
    return a;
}

#define SWZ128(off) ((off) ^ (((off) >> 3) & 0x70))

__device__ __forceinline__ void ldmx4(uint32_t* r, uint32_t addr) {
    asm volatile("ldmatrix.sync.aligned.m8n8.x4.shared.b16 {%0,%1,%2,%3}, [%4];"
        : "=r"(r[0]), "=r"(r[1]), "=r"(r[2]), "=r"(r[3]) : "r"(addr));
}
__device__ __forceinline__ void mma16816(float* d, const uint32_t* a, uint32_t b0, uint32_t b1) {
    asm volatile("mma.sync.aligned.m16n8k16.row.col.f32.bf16.bf16.f32 "
        "{%0,%1,%2,%3},{%4,%5,%6,%7},{%8,%9},{%0,%1,%2,%3};"
        : "+f"(d[0]), "+f"(d[1]), "+f"(d[2]), "+f"(d[3])
        : "r"(a[0]), "r"(a[1]), "r"(a[2]), "r"(a[3]), "r"(b0), "r"(b1));
}
__device__ __forceinline__ void cpasync16(uint32_t dst, const void* src) {
    asm volatile("cp.async.cg.shared.global [%0], [%1], 16;" :: "r"(dst), "l"(src) : "memory");
}

// ---------------- GEMM config ----------------
#define TM 128
#define TN 256
#define KC 64
#define NCH (DM / KC)   // 32 chunks
#define NSTG 3

// SMEM layout (bytes)
#define SM_QV   0                          // 256*32 f32 = 32768
#define SM_B1   (DH * 32 * 4)              // 32768 .. +1024
#define SM_STG  (SM_B1 + 1024)             // 33792 (1024-aligned)
#define SM_A    SM_STG                     // 3 * 16384
#define SM_B    (SM_STG + NSTG * TM * 128) // 82944, 3 * 32768
#define SMEM_SZ (SM_B + NSTG * TN * 128)   // 181248
#define YSTRIDE 257                        // padded y-tile row (floats)

extern "C" __global__ void __launch_bounds__(512, 1)
gemm_probe_kernel(const float* __restrict__ x, const float* __restrict__ b1)
{
    extern __shared__ char smem[];
    const uint32_t sb = smem_u32(smem);
    const int tid = threadIdx.x;
    const int wid = tid >> 5, lid = tid & 31;
    const long row0 = (long)blockIdx.x * TM;

    // stage qv table + bias (disjoint from pipeline stages; read only in epilogue)
    for (int i = tid; i < DH * 32; i += 512) ((float*)(smem + SM_QV))[i] = g_qvs[i];
    for (int i = tid; i < DH;      i += 512) ((float*)(smem + SM_B1))[i] = b1[i];

    // per-thread load mappings (constant across chunks)
    const float* aSrc[4]; uint32_t aOff[4];
    const char*  bSrc[4]; uint32_t bOff[4];
    #pragma unroll
    for (int i = 0; i < 4; i++) {
        const int u = tid + i * 512;
        const int r = u >> 4, cg = u & 15;          // A: 128 rows x 16 float4
        aSrc[i] = x + (row0 + r) * (long)DM + cg * 4;
        aOff[i] = SWZ128((uint32_t)(r * 128 + cg * 8));
        const int n = u >> 3, g = u & 7;            // B: 256 rows x 8 int4
        bSrc[i] = (const char*)g_w1bT + (long)n * (DM * 2) + g * 16;
        bOff[i] = SWZ128((uint32_t)(n * 128 + g * 16));
    }

    float4 af[4];
    // ---- prologue: chunk 0 (A direct LDG->cvt->STS, B cp.async) ----
    #pragma unroll
    for (int i = 0; i < 4; i++) af[i] = *(const float4*)(aSrc[i]);
    {
        char* ab = smem + SM_A;
        #pragma unroll
        for (int i = 0; i < 4; i++) {
            __nv_bfloat162 p0 = __float22bfloat162_rn(make_float2(af[i].x, af[i].y));
            __nv_bfloat162 p1 = __float22bfloat162_rn(make_float2(af[i].z, af[i].w));
            uint2 wv;
            wv.x = *reinterpret_cast<uint32_t*>(&p0);
            wv.y = *reinterpret_cast<uint32_t*>(&p1);
            *(uint2*)(ab + aOff[i]) = wv;
        }
        const uint32_t bb = sb + SM_B;
        #pragma unroll
        for (int i = 0; i < 4; i++) cpasync16(bb + bOff[i], bSrc[i]);
        asm volatile("cp.async.commit_group;" ::: "memory");
    }
    // ---- prologue: chunk 1 (A -> regs, B cp.async) ----
    #pragma unroll
    for (int i = 0; i < 4; i++) af[i] = *(const float4*)(aSrc[i] + KC);
    {
        const uint32_t bb = sb + SM_B + TN * 128;
        #pragma unroll
        for (int i = 0; i < 4; i++) cpasync16(bb + bOff[i], bSrc[i] + KC * 2);
        asm volatile("cp.async.commit_group;" ::: "memory");
    }

    const int mw = wid & 3, nw = wid >> 2;              // 4x4 warp grid
    const int lrow = lid & 15, lkb = (lid >> 4) * 16;   // ldmatrix lane mapping
    float acc[2][8][4];
    #pragma unroll
    for (int m = 0; m < 2; m++)
        #pragma unroll
        for (int t = 0; t < 8; t++)
            #pragma unroll
            for (int e = 0; e < 4; e++) acc[m][t][e] = 0.f;

    // ---- mainloop ----
    #pragma unroll 1
    for (int ch = 0; ch < NCH; ch++) {
        asm volatile("cp.async.wait_group 1;" ::: "memory");
        __syncthreads();
        const int s1 = (ch + 1) % NSTG, s2 = (ch + 2) % NSTG;
        if (ch + 1 < NCH) {                     // STS A(ch+1) from regs
            char* ab = smem + SM_A + s1 * (TM * 128);
            #pragma unroll
            for (int i = 0; i < 4; i++) {
                __nv_bfloat162 p0 = __float22bfloat162_rn(make_float2(af[i].x, af[i].y));
                __nv_bfloat162 p1 = __float22bfloat162_rn(make_float2(af[i].z, af[i].w));
                uint2 wv;
                wv.x = *reinterpret_cast<uint32_t*>(&p0);
                wv.y = *reinterpret_cast<uint32_t*>(&p1);
                *(uint2*)(ab + aOff[i]) = wv;
            }
        }
        if (ch + 2 < NCH) {                     // prefetch chunk ch+2
            const long k0 = (long)(ch + 2) * KC;
            #pragma unroll
            for (int i = 0; i < 4; i++) af[i] = *(const float4*)(aSrc[i] + k0);
            const uint32_t bb = sb + SM_B + s2 * (TN * 128);
            #pragma unroll
            for (int i = 0; i < 4; i++) cpasync16(bb + bOff[i], bSrc[i] + k0 * 2);
        }
        asm volatile("cp.async.commit_group;" ::: "memory");

        // compute chunk ch
        const uint32_t aB = sb + SM_A + (ch % NSTG) * (TM * 128);
        const uint32_t bB = sb + SM_B + (ch % NSTG) * (TN * 128);
        #pragma unroll
        for (int ks = 0; ks < 4; ks++) {
            uint32_t a[2][4], b[4][4];
            #pragma unroll
            for (int m = 0; m < 2; m++)
                ldmx4(a[m], aB + SWZ128((uint32_t)((mw * 32 + m * 16 + lrow) * 128 + ks * 32 + lkb)));
            #pragma unroll
            for (int j = 0; j < 4; j++)
                ldmx4(b[j], bB + SWZ128((uint32_t)((nw * 64 + j * 16 + lrow) * 128 + ks * 32 + lkb)));
            #pragma unroll
            for (int m = 0; m < 2; m++)
                #pragma unroll
                for (int j = 0; j < 4; j++) {
                    mma16816(acc[m][2 * j],     a[m], b[j][0], b[j][2]);
                    mma16816(acc[m][2 * j + 1], a[m], b[j][1], b[j][3]);
                }
        }
    }
    __syncthreads();

    // ---- epilogue: bias+relu, y -> padded SMEM tile ----
    float* yt = (float*)(smem + SM_STG);
    const float* b1s = (const float*)(smem + SM_B1);
    {
        const int g = lid >> 2, tg = lid & 3;
        #pragma unroll
        for (int m = 0; m < 2; m++)
            #pragma unroll
            for (int t = 0; t < 8; t++) {
                const int r = mw * 32 + m * 16 + g;
                const int c = nw * 64 + t * 8 + tg * 2;
                const float bc0 = b1s[c], bc1 = b1s[c + 1];
                yt[r * YSTRIDE + c]           = fmaxf(acc[m][t][0] + bc0, 0.f);
                yt[r * YSTRIDE + c + 1]       = fmaxf(acc[m][t][1] + bc1, 0.f);
                yt[(r + 8) * YSTRIDE + c]     = fmaxf(acc[m][t][2] + bc0, 0.f);
                yt[(r + 8) * YSTRIDE + c + 1] = fmaxf(acc[m][t][3] + bc1, 0.f);
            }
    }
    __syncthreads();

    // ---- epilogue: 32 head dot-products per row, 4 col-parts per row ----
    {
        const int row = tid & 127, part = tid >> 7;   // warp = 32 consecutive rows, same part
        const float* yr = yt + row * YSTRIDE + part * 64;
        const float* qv = (const float*)(smem + SM_QV);
        float accL[16], accV[16];
        #pragma unroll
        for (int j = 0; j < 16; j++) { accL[j] = 0.f; accV[j] = 0.f; }
        #pragma unroll 4
        for (int c = 0; c < 64; c++) {
            const float y = yr[c];
            const float4* qvr = (const float4*)(qv + (part * 64 + c) * 32);
            #pragma unroll
            for (int q4 = 0; q4 < 4; q4++) {
                const float4 qq = qvr[q4];
                const float4 vv = qvr[4 + q4];
                accL[q4 * 4 + 0] = fmaf(y, qq.x, accL[q4 * 4 + 0]);
                accL[q4 * 4 + 1] = fmaf(y, qq.y, accL[q4 * 4 + 1]);
                accL[q4 * 4 + 2] = fmaf(y, qq.z, accL[q4 * 4 + 2]);
                accL[q4 * 4 + 3] = fmaf(y, qq.w, accL[q4 * 4 + 3]);
                accV[q4 * 4 + 0] = fmaf(y, vv.x, accV[q4 * 4 + 0]);
                accV[q4 * 4 + 1] = fmaf(y, vv.y, accV[q4 * 4 + 1]);
                accV[q4 * 4 + 2] = fmaf(y, vv.z, accV[q4 * 4 + 2]);
                accV[q4 * 4 + 3] = fmaf(y, vv.w, accV[q4 * 4 + 3]);
            }
        }
        __syncthreads();
        if (part) {                                    // parts 1..3 park partials in y-tile
            float* dst = yt + row * YSTRIDE + part * 64;
            #pragma unroll
            for (int j = 0; j < 16; j++) { dst[j] = accL[j]; dst[16 + j] = accV[j]; }
        }
        __syncthreads();
        if (part == 0) {
            #pragma unroll
            for (int p = 1; p < 4; p++) {
                const float* src = yt + row * YSTRIDE + p * 64;
                #pragma unroll
                for (int j = 0; j < 16; j++) { accL[j] += src[j]; accV[j] += src[16 + j]; }
            }
            const long rw = row0 + row;
            #pragma unroll
            for (int j = 0; j < 16; j++) {
                g_logitsT[(long)j * NT + rw] = accL[j];
                g_valsT[(long)j * NT + rw]   = accV[j];
            }
        }
    }
}

// ---------------- prep kernels ----------------
__global__ void prep_w1_kernel(const float* __restrict__ w1) {
    __shared__ float tile[32][33];
    const int nb = blockIdx.x * 32, kb = blockIdx.y * 32;
    for (int r = threadIdx.y; r < 32; r += 8)
        tile[r][threadIdx.x] = w1[(long)(kb + r) * DH + nb + threadIdx.x];
    __syncthreads();
    for (int r = threadIdx.y; r < 32; r += 8)
        g_w1bT[(long)(nb + r) * DM + kb + threadIdx.x] = __float2bfloat16(tile[threadIdx.x][r]);
}

__global__ void prep_qv_kernel(const float* __restrict__ q, const float* __restrict__ v) {
    const int i = blockIdx.x * 256 + threadIdx.x;   // < 4096
    const int h = i & 15, c = i >> 4;
    g_qvs[c * 32 + h]      = q[h * DH + c];
    g_qvs[c * 32 + 16 + h] = v[h * DH + c];
    if (blockIdx.x == 0 && threadIdx.x < NH) g_headmax[threadIdx.x] = 0u;
}

// ---------------- windowed softmax-mean + max ----------------
__device__ __forceinline__ unsigned f2key(float f) {
    unsigned u = __float_as_uint(f);
    return (u & 0x80000000u) ? ~u : (u | 0x80000000u);
}
__device__ __forceinline__ float key2f(unsigned k) {
    unsigned u = (k & 0x80000000u) ? (k & 0x7FFFFFFFu) : ~k;
    return __uint_as_float(u);
}

#define SPAN 2048
__global__ void __launch_bounds__(256, 4)
window_kernel(const int* __restrict__ wsz)
{
    __shared__ float2 buf[1 + SPAN + WMAX];   // prefix sums of (e, e*v)
    __shared__ float2 tot[256];
    __shared__ float  wmax[8];

    const int h = blockIdx.y;
    const long base = (long)blockIdx.x * SPAN;
    const int t = threadIdx.x;
    int w = wsz ? wsz[0] : WMAX;
    if (w > WMAX) w = WMAX;
    if (w < 1) w = 1;
    const int load = (int)min((long)(SPAN + w - 1), (long)NT - base);

    const float* lg = g_logitsT + (long)h * NT + base;
    const float* vl = g_valsT   + (long)h * NT + base;

    if (t == 0) buf[0] = make_float2(0.f, 0.f);
    for (int i = t; i < load; i += 256) {
        const float e = expf(lg[i]);
        buf[1 + i] = make_float2(e, e * vl[i]);
    }
    __syncthreads();

    // block scan: local scan of 9, Hillis-Steele on totals
    const int s0 = 1 + t * 9;
    const int s1 = min(s0 + 9, 1 + load);
    float2 run = make_float2(0.f, 0.f);
    for (int i = s0; i < s1; i++) { run.x += buf[i].x; run.y += buf[i].y; buf[i] = run; }
    tot[t] = run;
    __syncthreads();
    for (int off = 1; off < 256; off <<= 1) {
        float2 add = make_float2(0.f, 0.f);
        if (t >= off) add = tot[t - off];
        __syncthreads();
        tot[t].x += add.x; tot[t].y += add.y;
        __syncthreads();
    }
    float2 offv = (t > 0) ? tot[t - 1] : make_float2(0.f, 0.f);
    for (int i = s0; i < s1; i++) { buf[i].x += offv.x; buf[i].y += offv.y; }
    __syncthreads();

    float best = -3.402823466e38f;
    for (int a = t; a < SPAN; a += 256) {
        if (a + w <= load) {
            const float2 hi = buf[a + w];
            const float2 lo = buf[a];
            best = fmaxf(best, (hi.y - lo.y) / (hi.x - lo.x));
        }
    }
    #pragma unroll
    for (int o = 16; o; o >>= 1) best = fmaxf(best, __shfl_xor_sync(0xFFFFFFFFu, best, o));
    if ((t & 31) == 0) wmax[t >> 5] = best;
    __syncthreads();
    if (t == 0) {
        float m = wmax[0];
        #pragma unroll
        for (int i = 1; i < 8; i++) m = fmaxf(m, wmax[i]);
        atomicMax(&g_headmax[h], f2key(m));
    }
}

__global__ void final_kernel(float* __restrict__ out) {
    if (threadIdx.x == 0) {
        float s = 0.f;
        #pragma unroll
        for (int hh = 0; hh < NH; hh++) s += key2f(g_headmax[hh]);
        out[0] = s;
    }
}

// ---------------- launch ----------------
extern "C" void kernel_launch(void* const* d_in, const int* in_sizes, int n_in,
                              void* d_out, int out_size)
{
    const float* x  = (const float*)d_in[0];
    const float* w1 = (const float*)d_in[1];
    const float* b1 = (const float*)d_in[2];
    const float* q  = (const float*)d_in[3];
    const float* v  = (const float*)d_in[4];
    const int* wsz  = (n_in > 5) ? (const int*)d_in[5] : nullptr;

    cudaFuncSetAttribute(gemm_probe_kernel, cudaFuncAttributeMaxDynamicSharedMemorySize, SMEM_SZ);

    prep_w1_kernel<<<dim3(DH / 32, DM / 32), dim3(32, 8)>>>(w1);
    prep_qv_kernel<<<16, 256>>>(q, v);
    gemm_probe_kernel<<<NT / TM, 512, SMEM_SZ>>>(x, b1);
    window_kernel<<<dim3(NT / SPAN, NH), 256>>>(wsz);
    final_kernel<<<1, 32>>>((float*)d_out);
}

// round 9
// speedup vs baseline: 1.4489x; 1.4489x over previous
#include <cuda_runtime.h>
#include <cuda_bf16.h>
#include <cstdint>

// ---------------- problem constants ----------------
#define NT 131072     // tokens
#define DM 2048       // d_model
#define DH 256        // d_hid
#define NH 16         // heads
#define WMAX 64       // window

// ---------------- scratch (device globals; no allocs allowed) ----------------
__device__ __nv_bfloat16 g_w1bT[(size_t)DH * DM];  // [n][k] bf16
__device__ __nv_bfloat16 g_qvb[32 * DH];           // [j][k]: j<16 -> q[j], j>=16 -> v[j-16]
__device__ float g_logitsT[(size_t)NH * NT];       // [h][token]
__device__ float g_valsT[(size_t)NH * NT];         // [h][token]
__device__ unsigned int g_headmax[NH];             // order-preserving float keys

// ---------------- helpers ----------------
__device__ __forceinline__ uint32_t smem_u32(const void* p) {
    uint32_t a;
    asm("{ .reg .u64 t; cvta.to.shared.u64 t, %1; cvt.u32.u64 %0, t; }" : "=r"(a) : "l"(p));
    return a;
}

#define SWZ128(off) ((off) ^ (((off) >> 3) & 0x70))   // 128B-row tiles
#define SWZ512(off) ((off) ^ (((off) >> 5) & 0x70))   // 512B-row tiles (row LSBs at bit 9)

__device__ __forceinline__ void ldmx4(uint32_t* r, uint32_t addr) {
    asm volatile("ldmatrix.sync.aligned.m8n8.x4.shared.b16 {%0,%1,%2,%3}, [%4];"
        : "=r"(r[0]), "=r"(r[1]), "=r"(r[2]), "=r"(r[3]) : "r"(addr));
}
__device__ __forceinline__ void mma16816(float* d, const uint32_t* a, uint32_t b0, uint32_t b1) {
    asm volatile("mma.sync.aligned.m16n8k16.row.col.f32.bf16.bf16.f32 "
        "{%0,%1,%2,%3},{%4,%5,%6,%7},{%8,%9},{%0,%1,%2,%3};"
        : "+f"(d[0]), "+f"(d[1]), "+f"(d[2]), "+f"(d[3])
        : "r"(a[0]), "r"(a[1]), "r"(a[2]), "r"(a[3]), "r"(b0), "r"(b1));
}
__device__ __forceinline__ void cpasync16(uint32_t dst, const void* src) {
    asm volatile("cp.async.cg.shared.global [%0], [%1], 16;" :: "r"(dst), "l"(src) : "memory");
}
__device__ __forceinline__ float4 ldcs4(const float* p) {
    float4 v;
    asm volatile("ld.global.cs.v4.f32 {%0,%1,%2,%3}, [%4];"
        : "=f"(v.x), "=f"(v.y), "=f"(v.z), "=f"(v.w) : "l"(p));
    return v;
}

// ---------------- GEMM config ----------------
#define TM 128
#define TN 256
#define KC 64
#define NCH (DM / KC)   // 32 chunks
#define NSTG 3

// SMEM layout (bytes)
#define SM_A   0                               // 3 * 16384 = 49152
#define SM_B   (NSTG * TM * KC * 2)            // 49152, 3 * 32768 = 98304
#define SM_B1  (SM_B + NSTG * TN * KC * 2)     // 147456, 1KB
#define SMEM_SZ (SM_B1 + 1024)                 // 148480
// epilogue overlays (stage buffers are dead by then)
#define SM_Y   0                               // 128 x 256 bf16 = 65536 (rows 512B, SWZ512)
#define SM_QV  65536                           // 32 x 256 bf16 = 16384 (rows 512B, SWZ512)

extern "C" __global__ void __launch_bounds__(256, 1)
gemm_probe_kernel(const float* __restrict__ x, const float* __restrict__ b1)
{
    extern __shared__ char smem[];
    const uint32_t sb = smem_u32(smem);
    const int tid = threadIdx.x;
    const int wid = tid >> 5, lid = tid & 31;
    const long row0 = (long)blockIdx.x * TM;

    ((float*)(smem + SM_B1))[tid] = b1[tid];   // 256 threads == DH

    // per-thread load mappings (8 pieces each for A and B)
    uint32_t aSrc[8], aOff[8], bSrc[8], bOff[8];
    #pragma unroll
    for (int i = 0; i < 8; i++) {
        const int u = tid + i * 256;
        const int r = u >> 4, cg = u & 15;          // A: 128 rows x 16 float4
        aSrc[i] = (uint32_t)(r * DM + cg * 4);      // element offset within x block
        aOff[i] = SWZ128((uint32_t)(r * 128 + cg * 8));
        const int n = u >> 3, g = u & 7;            // B: 256 rows x 8 int4
        bSrc[i] = (uint32_t)(n * (DM * 2) + g * 16);// byte offset within g_w1bT
        bOff[i] = SWZ128((uint32_t)(n * 128 + g * 16));
    }
    const float* xb = x + row0 * (long)DM;
    const char*  wb = (const char*)g_w1bT;

    float4 af[8];
    // ---- prologue ----
    {   // B chunk 0
        const uint32_t bb = sb + SM_B;
        #pragma unroll
        for (int i = 0; i < 8; i++) cpasync16(bb + bOff[i], wb + bSrc[i]);
        asm volatile("cp.async.commit_group;" ::: "memory");
    }
    #pragma unroll
    for (int i = 0; i < 8; i++) af[i] = ldcs4(xb + aSrc[i]);   // A chunk 0
    {   // STS A0
        char* ab = smem + SM_A;
        #pragma unroll
        for (int i = 0; i < 8; i++) {
            __nv_bfloat162 p0 = __float22bfloat162_rn(make_float2(af[i].x, af[i].y));
            __nv_bfloat162 p1 = __float22bfloat162_rn(make_float2(af[i].z, af[i].w));
            uint2 wv;
            wv.x = *reinterpret_cast<uint32_t*>(&p0);
            wv.y = *reinterpret_cast<uint32_t*>(&p1);
            *(uint2*)(ab + aOff[i]) = wv;
        }
    }
    {   // B chunk 1
        const uint32_t bb = sb + SM_B + TN * KC * 2;
        #pragma unroll
        for (int i = 0; i < 8; i++) cpasync16(bb + bOff[i], wb + bSrc[i] + KC * 2);
        asm volatile("cp.async.commit_group;" ::: "memory");
    }
    #pragma unroll
    for (int i = 0; i < 8; i++) af[i] = ldcs4(xb + aSrc[i] + KC);  // A chunk 1

    const int mw = wid & 1, nw = wid >> 1;              // 2x4 warp grid, 64x64 tiles
    const int lrow = lid & 15, lkb = (lid >> 4) * 16;   // ldmatrix lane mapping
    float acc[4][8][4];
    #pragma unroll
    for (int m = 0; m < 4; m++)
        #pragma unroll
        for (int t = 0; t < 8; t++)
            #pragma unroll
            for (int e = 0; e < 4; e++) acc[m][t][e] = 0.f;

    // ---- mainloop ----
    #pragma unroll 1
    for (int ch = 0; ch < NCH; ch++) {
        asm volatile("cp.async.wait_group 1;" ::: "memory");
        __syncthreads();
        const int s1 = (ch + 1) % NSTG, s2 = (ch + 2) % NSTG;
        if (ch + 1 < NCH) {                     // STS A(ch+1) from regs
            char* ab = smem + SM_A + s1 * (TM * KC * 2);
            #pragma unroll
            for (int i = 0; i < 8; i++) {
                __nv_bfloat162 p0 = __float22bfloat162_rn(make_float2(af[i].x, af[i].y));
                __nv_bfloat162 p1 = __float22bfloat162_rn(make_float2(af[i].z, af[i].w));
                uint2 wv;
                wv.x = *reinterpret_cast<uint32_t*>(&p0);
                wv.y = *reinterpret_cast<uint32_t*>(&p1);
                *(uint2*)(ab + aOff[i]) = wv;
            }
        }
        if (ch + 2 < NCH) {                     // prefetch chunk ch+2
            const int k0 = (ch + 2) * KC;
            #pragma unroll
            for (int i = 0; i < 8; i++) af[i] = ldcs4(xb + aSrc[i] + k0);
            const uint32_t bb = sb + SM_B + s2 * (TN * KC * 2);
            #pragma unroll
            for (int i = 0; i < 8; i++) cpasync16(bb + bOff[i], wb + bSrc[i] + k0 * 2);
        }
        asm volatile("cp.async.commit_group;" ::: "memory");

        // compute chunk ch
        const uint32_t aB = sb + SM_A + (ch % NSTG) * (TM * KC * 2);
        const uint32_t bB = sb + SM_B + (ch % NSTG) * (TN * KC * 2);
        #pragma unroll
        for (int ks = 0; ks < 4; ks++) {
            uint32_t a[4][4], b[4][4];
            #pragma unroll
            for (int mt = 0; mt < 4; mt++)
                ldmx4(a[mt], aB + SWZ128((uint32_t)((mw * 64 + mt * 16 + lrow) * 128 + ks * 32 + lkb)));
            #pragma unroll
            for (int nt = 0; nt < 4; nt++)
                ldmx4(b[nt], bB + SWZ128((uint32_t)((nw * 64 + nt * 16 + lrow) * 128 + ks * 32 + lkb)));
            #pragma unroll
            for (int mt = 0; mt < 4; mt++)
                #pragma unroll
                for (int nt = 0; nt < 4; nt++) {
                    mma16816(acc[mt][2 * nt],     a[mt], b[nt][0], b[nt][2]);
                    mma16816(acc[mt][2 * nt + 1], a[mt], b[nt][1], b[nt][3]);
                }
        }
    }
    __syncthreads();   // mainloop done; stage smem is dead

    // ---- epilogue A: bias+relu, y -> SMEM as bf16 (512B rows, SWZ512) ----
    {
        const float* b1s = (const float*)(smem + SM_B1);
        char* yb = smem + SM_Y;
        const int g4 = lid >> 2, t4 = lid & 3;
        #pragma unroll
        for (int mt = 0; mt < 4; mt++)
            #pragma unroll
            for (int t = 0; t < 8; t++) {
                const int r = mw * 64 + mt * 16 + g4;
                const int c = nw * 64 + t * 8 + t4 * 2;
                const float bc0 = b1s[c], bc1 = b1s[c + 1];
                __nv_bfloat162 y0 = __float22bfloat162_rn(make_float2(
                    fmaxf(acc[mt][t][0] + bc0, 0.f), fmaxf(acc[mt][t][1] + bc1, 0.f)));
                __nv_bfloat162 y1 = __float22bfloat162_rn(make_float2(
                    fmaxf(acc[mt][t][2] + bc0, 0.f), fmaxf(acc[mt][t][3] + bc1, 0.f)));
                *(uint32_t*)(yb + SWZ512((uint32_t)(r * 512 + c * 2)))       = *reinterpret_cast<uint32_t*>(&y0);
                *(uint32_t*)(yb + SWZ512((uint32_t)((r + 8) * 512 + c * 2))) = *reinterpret_cast<uint32_t*>(&y1);
            }
        // stage QV (32 x 256 bf16) into SMEM, same layout
        char* qb = smem + SM_QV;
        #pragma unroll
        for (int i = 0; i < 4; i++) {
            const int u = tid + i * 256;             // 1024 int4
            const int n = u >> 5, g = u & 31;
            const uint32_t off = (uint32_t)(n * 512 + g * 16);
            *(int4*)(qb + SWZ512(off)) = *(const int4*)((const char*)g_qvb + off);
        }
    }
    __syncthreads();

    // ---- epilogue B: [logits|vals](128x32) = Y(128x256) @ QV^T via tensor cores ----
    {
        float d[4][4];
        #pragma unroll
        for (int i = 0; i < 4; i++)
            #pragma unroll
            for (int e = 0; e < 4; e++) d[i][e] = 0.f;
        const uint32_t yB = sb + SM_Y, qB = sb + SM_QV;
        #pragma unroll
        for (int ks = 0; ks < 16; ks++) {
            uint32_t a[4], b0[4], b1r[4];
            ldmx4(a,   yB + SWZ512((uint32_t)((wid * 16 + lrow) * 512 + ks * 32 + lkb)));
            ldmx4(b0,  qB + SWZ512((uint32_t)(lrow * 512 + ks * 32 + lkb)));          // n 0-15
            ldmx4(b1r, qB + SWZ512((uint32_t)((16 + lrow) * 512 + ks * 32 + lkb)));   // n 16-31
            mma16816(d[0], a, b0[0],  b0[2]);
            mma16816(d[1], a, b0[1],  b0[3]);
            mma16816(d[2], a, b1r[0], b1r[2]);
            mma16816(d[3], a, b1r[1], b1r[3]);
        }
        const long r0 = row0 + wid * 16 + (lid >> 2);
        #pragma unroll
        for (int nt2 = 0; nt2 < 4; nt2++) {
            const int j = nt2 * 8 + (lid & 3) * 2;   // pairs never straddle 16
            float* base = (j < 16) ? (g_logitsT + (long)j * NT) : (g_valsT + (long)(j - 16) * NT);
            base[r0]          = d[nt2][0];
            base[NT + r0]     = d[nt2][1];
            base[r0 + 8]      = d[nt2][2];
            base[NT + r0 + 8] = d[nt2][3];
        }
    }
}

// ---------------- prep kernels ----------------
__global__ void prep_w1_kernel(const float* __restrict__ w1) {
    __shared__ float tile[32][33];
    const int nb = blockIdx.x * 32, kb = blockIdx.y * 32;
    for (int r = threadIdx.y; r < 32; r += 8)
        tile[r][threadIdx.x] = w1[(long)(kb + r) * DH + nb + threadIdx.x];
    __syncthreads();
    for (int r = threadIdx.y; r < 32; r += 8)
        g_w1bT[(long)(nb + r) * DM + kb + threadIdx.x] = __float2bfloat16(tile[threadIdx.x][r]);
}

__global__ void prep_qv_kernel(const float* __restrict__ q, const float* __restrict__ v) {
    const int i = blockIdx.x * 256 + threadIdx.x;   // 8192 elements
    const int j = i >> 8, k = i & 255;
    const float val = (j < 16) ? q[j * DH + k] : v[(j - 16) * DH + k];
    g_qvb[j * DH + k] = __float2bfloat16(val);
    if (blockIdx.x == 0 && threadIdx.x < NH) g_headmax[threadIdx.x] = 0u;
}

// ---------------- windowed softmax-mean + max ----------------
__device__ __forceinline__ unsigned f2key(float f) {
    unsigned u = __float_as_uint(f);
    return (u & 0x80000000u) ? ~u : (u | 0x80000000u);
}
__device__ __forceinline__ float key2f(unsigned k) {
    unsigned u = (k & 0x80000000u) ? (k & 0x7FFFFFFFu) : ~k;
    return __uint_as_float(u);
}

#define SPAN 2048
__global__ void __launch_bounds__(256, 4)
window_kernel(const int* __restrict__ wsz)
{
    __shared__ float2 buf[1 + SPAN + WMAX];   // prefix sums of (e, e*v)
    __shared__ float2 tot[256];
    __shared__ float  wmax[8];

    const int h = blockIdx.y;
    const long base = (long)blockIdx.x * SPAN;
    const int t = threadIdx.x;
    int w = wsz ? wsz[0] : WMAX;
    if (w > WMAX) w = WMAX;
    if (w < 1) w = 1;
    const int load = (int)min((long)(SPAN + w - 1), (long)NT - base);

    const float* lg = g_logitsT + (long)h * NT + base;
    const float* vl = g_valsT   + (long)h * NT + base;

    if (t == 0) buf[0] = make_float2(0.f, 0.f);
    for (int i = t; i < load; i += 256) {
        const float e = expf(lg[i]);
        buf[1 + i] = make_float2(e, e * vl[i]);
    }
    __syncthreads();

    const int s0 = 1 + t * 9;
    const int s1 = min(s0 + 9, 1 + load);
    float2 run = make_float2(0.f, 0.f);
    for (int i = s0; i < s1; i++) { run.x += buf[i].x; run.y += buf[i].y; buf[i] = run; }
    tot[t] = run;
    __syncthreads();
    for (int off = 1; off < 256; off <<= 1) {
        float2 add = make_float2(0.f, 0.f);
        if (t >= off) add = tot[t - off];
        __syncthreads();
        tot[t].x += add.x; tot[t].y += add.y;
        __syncthreads();
    }
    float2 offv = (t > 0) ? tot[t - 1] : make_float2(0.f, 0.f);
    for (int i = s0; i < s1; i++) { buf[i].x += offv.x; buf[i].y += offv.y; }
    __syncthreads();

    float best = -3.402823466e38f;
    for (int a = t; a < SPAN; a += 256) {
        if (a + w <= load) {
            const float2 hi = buf[a + w];
            const float2 lo = buf[a];
            best = fmaxf(best, (hi.y - lo.y) / (hi.x - lo.x));
        }
    }
    #pragma unroll
    for (int o = 16; o; o >>= 1) best = fmaxf(best, __shfl_xor_sync(0xFFFFFFFFu, best, o));
    if ((t & 31) == 0) wmax[t >> 5] = best;
    __syncthreads();
    if (t == 0) {
        float m = wmax[0];
        #pragma unroll
        for (int i = 1; i < 8; i++) m = fmaxf(m, wmax[i]);
        atomicMax(&g_headmax[h], f2key(m));
    }
}

__global__ void final_kernel(float* __restrict__ out) {
    if (threadIdx.x == 0) {
        float s = 0.f;
        #pragma unroll
        for (int hh = 0; hh < NH; hh++) s += key2f(g_headmax[hh]);
        out[0] = s;
    }
}

// ---------------- launch ----------------
extern "C" void kernel_launch(void* const* d_in, const int* in_sizes, int n_in,
                              void* d_out, int out_size)
{
    const float* x  = (const float*)d_in[0];
    const float* w1 = (const float*)d_in[1];
    const float* b1 = (const float*)d_in[2];
    const float* q  = (const float*)d_in[3];
    const float* v  = (const float*)d_in[4];
    const int* wsz  = (n_in > 5) ? (const int*)d_in[5] : nullptr;

    cudaFuncSetAttribute(gemm_probe_kernel, cudaFuncAttributeMaxDynamicSharedMemorySize, SMEM_SZ);

    prep_w1_kernel<<<dim3(DH / 32, DM / 32), dim3(32, 8)>>>(w1);
    prep_qv_kernel<<<32, 256>>>(q, v);
    gemm_probe_kernel<<<NT / TM, 256, SMEM_SZ>>>(x, b1);
    window_kernel<<<dim3(NT / SPAN, NH), 256>>>(wsz);
    final_kernel<<<1, 32>>>((float*)d_out);
}